// round 10
// baseline (speedup 1.0000x reference)
#include <cuda_runtime.h>

// WarpDTI fused: trilinear warp (border, align_corners) of 6-ch DTI +
// Jacobian of DDF + reorientation S = R^T M R, R = polar factor of J.
//
// R9 optimization: a memory-layout prepass interleaves
//   dti (B,6,H,W,D)  -> g_dti_i[vox] = 8 floats (6 tensor comps + pad), 32B aligned
//   ddf (B,3,H,W,D)  -> g_ddf_i[vox] = float4 (3 comps + pad)
// so the main kernel's scattered trilinear gather is 2x LDG.128 per corner
// (16 loads) instead of 48 scalar LDGs, and the Jacobian stencil is 7x
// LDG.128 instead of 21 scalar LDGs. Polar iteration: 2 scaled Newton steps
// (Frobenius mu) + 4 plain Newton steps (quadratic, mu ~= 1 by then).

constexpr int HWD  = 64 * 64 * 64;   // 262144 = 2^18
constexpr int MAXB = 2;

__device__ float4 g_dti_i[(size_t)MAXB * HWD * 2];  // 16 MB
__device__ float4 g_ddf_i[(size_t)MAXB * HWD];      //  8 MB

__global__ __launch_bounds__(256)
void interleave_kernel(const float* __restrict__ dti,
                       const float* __restrict__ ddf,
                       int total)
{
    int idx = blockIdx.x * blockDim.x + threadIdx.x;
    if (idx >= total) return;
    int vox = idx & (HWD - 1);
    int b   = idx >> 18;

    const float* p = dti + (size_t)b * 6 * HWD + vox;
    float m0 = __ldg(p);
    float m1 = __ldg(p +     HWD);
    float m2 = __ldg(p + 2 * HWD);
    float m3 = __ldg(p + 3 * HWD);
    float m4 = __ldg(p + 4 * HWD);
    float m5 = __ldg(p + 5 * HWD);
    const float* q = ddf + (size_t)b * 3 * HWD + vox;
    float u0 = __ldg(q);
    float u1 = __ldg(q +     HWD);
    float u2 = __ldg(q + 2 * HWD);

    g_dti_i[(size_t)idx * 2]     = make_float4(m0, m1, m2, m3);
    g_dti_i[(size_t)idx * 2 + 1] = make_float4(m4, m5, 0.f, 0.f);
    g_ddf_i[idx]                 = make_float4(u0, u1, u2, 0.f);
}

__global__ __launch_bounds__(256)
void warp_dti_kernel(float* __restrict__ out, int total)
{
    int idx = blockIdx.x * blockDim.x + threadIdx.x;
    if (idx >= total) return;

    int vox = idx & (HWD - 1);
    int b   = idx >> 18;
    int z   =  vox        & 63;
    int y   = (vox >> 6)  & 63;
    int x   =  vox >> 12;

    const float4* ddf_i = g_ddf_i + (size_t)b * HWD;

    // ---------- center displacement ----------
    float4 uc = __ldg(ddf_i + vox);

    // ---------- Jacobian J = I + du_i/dx_j (jnp.gradient semantics) --------
    float J00, J01, J02, J10, J11, J12, J20, J21, J22;
    {   // axis 0 (x), voxel stride 4096
        int ip = (x < 63) ? x + 1 : 63;
        int im = (x > 0 ) ? x - 1 : 0;
        float s = (ip - im == 2) ? 0.5f : 1.0f;
        float4 up = __ldg(ddf_i + vox + ((ip - x) << 12));
        float4 um = __ldg(ddf_i + vox + ((im - x) << 12));
        J00 = (up.x - um.x) * s; J10 = (up.y - um.y) * s; J20 = (up.z - um.z) * s;
    }
    {   // axis 1 (y), voxel stride 64
        int ip = (y < 63) ? y + 1 : 63;
        int im = (y > 0 ) ? y - 1 : 0;
        float s = (ip - im == 2) ? 0.5f : 1.0f;
        float4 up = __ldg(ddf_i + vox + ((ip - y) << 6));
        float4 um = __ldg(ddf_i + vox + ((im - y) << 6));
        J01 = (up.x - um.x) * s; J11 = (up.y - um.y) * s; J21 = (up.z - um.z) * s;
    }
    {   // axis 2 (z), voxel stride 1
        int ip = (z < 63) ? z + 1 : 63;
        int im = (z > 0 ) ? z - 1 : 0;
        float s = (ip - im == 2) ? 0.5f : 1.0f;
        float4 up = __ldg(ddf_i + vox + (ip - z));
        float4 um = __ldg(ddf_i + vox + (im - z));
        J02 = (up.x - um.x) * s; J12 = (up.y - um.y) * s; J22 = (up.z - um.z) * s;
    }
    J00 += 1.0f; J11 += 1.0f; J22 += 1.0f;

    // ---------- trilinear warp (border clamp, align_corners) ----------
    float cx = fminf(fmaxf(uc.x + (float)x, 0.0f), 63.0f);
    float cy = fminf(fmaxf(uc.y + (float)y, 0.0f), 63.0f);
    float cz = fminf(fmaxf(uc.z + (float)z, 0.0f), 63.0f);
    float xf = floorf(cx), yf = floorf(cy), zf = floorf(cz);
    float fx = cx - xf,   fy = cy - yf,   fz = cz - zf;
    int x0 = (int)xf, y0 = (int)yf, z0 = (int)zf;
    int x1 = min(x0 + 1, 63), y1 = min(y0 + 1, 63), z1 = min(z0 + 1, 63);

    int c000 = ((x0 << 6) + y0) * 64 + z0;
    int c001 = ((x0 << 6) + y0) * 64 + z1;
    int c010 = ((x0 << 6) + y1) * 64 + z0;
    int c011 = ((x0 << 6) + y1) * 64 + z1;
    int c100 = ((x1 << 6) + y0) * 64 + z0;
    int c101 = ((x1 << 6) + y0) * 64 + z1;
    int c110 = ((x1 << 6) + y1) * 64 + z0;
    int c111 = ((x1 << 6) + y1) * 64 + z1;

    float wx0 = 1.0f - fx, wy0 = 1.0f - fy, wz0 = 1.0f - fz;
    float wgt[8] = { wx0 * wy0 * wz0, wx0 * wy0 * fz,
                     wx0 * fy  * wz0, wx0 * fy  * fz,
                     fx  * wy0 * wz0, fx  * wy0 * fz,
                     fx  * fy  * wz0, fx  * fy  * fz };
    int   cid[8] = { c000, c001, c010, c011, c100, c101, c110, c111 };

    const float4* dti_i = g_dti_i + (size_t)b * HWD * 2;
    float m0 = 0.f, m1 = 0.f, m2 = 0.f, m3 = 0.f, m4 = 0.f, m5 = 0.f;
    #pragma unroll
    for (int k = 0; k < 8; k++) {
        const float4* p = dti_i + ((size_t)cid[k] << 1);
        float4 A = __ldg(p);
        float4 Bv = __ldg(p + 1);
        float w = wgt[k];
        m0 = fmaf(w, A.x,  m0);
        m1 = fmaf(w, A.y,  m1);
        m2 = fmaf(w, A.z,  m2);
        m3 = fmaf(w, A.w,  m3);
        m4 = fmaf(w, Bv.x, m4);
        m5 = fmaf(w, Bv.y, m5);
    }

    // ---------- polar factor R = U V^T ----------
    float X00 = J00, X01 = J01, X02 = J02;
    float X10 = J10, X11 = J11, X12 = J12;
    float X20 = J20, X21 = J21, X22 = J22;

    // 2 scaled Newton iterations (Frobenius-norm mu) ...
    #pragma unroll
    for (int it = 0; it < 2; ++it) {
        float C00 = X11 * X22 - X12 * X21;
        float C01 = X12 * X20 - X10 * X22;
        float C02 = X10 * X21 - X11 * X20;
        float C10 = X21 * X02 - X22 * X01;
        float C11 = X22 * X00 - X20 * X02;
        float C12 = X20 * X01 - X21 * X00;
        float C20 = X01 * X12 - X02 * X11;
        float C21 = X02 * X10 - X00 * X12;
        float C22 = X00 * X11 - X01 * X10;
        float det = X00 * C00 + X01 * C01 + X02 * C02;
        float adet = fmaxf(fabsf(det), 1e-12f);
        float sdet = (det < 0.0f) ? -adet : adet;
        float nX = X00*X00 + X01*X01 + X02*X02 + X10*X10 + X11*X11 + X12*X12
                 + X20*X20 + X21*X21 + X22*X22;
        float nC = C00*C00 + C01*C01 + C02*C02 + C10*C10 + C11*C11 + C12*C12
                 + C20*C20 + C21*C21 + C22*C22;
        float mu = sqrtf(sqrtf(nC / nX) / adet);
        mu = fminf(fmaxf(mu, 1e-4f), 1e4f);
        float a = 0.5f * mu;
        float c = 0.5f / (mu * sdet);
        X00 = a * X00 + c * C00; X01 = a * X01 + c * C01; X02 = a * X02 + c * C02;
        X10 = a * X10 + c * C10; X11 = a * X11 + c * C11; X12 = a * X12 + c * C12;
        X20 = a * X20 + c * C20; X21 = a * X21 + c * C21; X22 = a * X22 + c * C22;
    }
    // ... then 4 plain Newton iterations (mu == 1): X <- 0.5*(X + C/det)
    #pragma unroll
    for (int it = 0; it < 4; ++it) {
        float C00 = X11 * X22 - X12 * X21;
        float C01 = X12 * X20 - X10 * X22;
        float C02 = X10 * X21 - X11 * X20;
        float C10 = X21 * X02 - X22 * X01;
        float C11 = X22 * X00 - X20 * X02;
        float C12 = X20 * X01 - X21 * X00;
        float C20 = X01 * X12 - X02 * X11;
        float C21 = X02 * X10 - X00 * X12;
        float C22 = X00 * X11 - X01 * X10;
        float det = X00 * C00 + X01 * C01 + X02 * C02;
        float adet = fmaxf(fabsf(det), 1e-12f);
        float sdet = (det < 0.0f) ? -adet : adet;
        float c = 0.5f / sdet;
        X00 = 0.5f * X00 + c * C00; X01 = 0.5f * X01 + c * C01; X02 = 0.5f * X02 + c * C02;
        X10 = 0.5f * X10 + c * C10; X11 = 0.5f * X11 + c * C11; X12 = 0.5f * X12 + c * C12;
        X20 = 0.5f * X20 + c * C20; X21 = 0.5f * X21 + c * C21; X22 = 0.5f * X22 + c * C22;
    }

    // ---------- S = R^T M R, lower triangle ----------
    float w0x = m0*X00 + m1*X10 + m3*X20;
    float w0y = m1*X00 + m2*X10 + m4*X20;
    float w0z = m3*X00 + m4*X10 + m5*X20;
    float w1x = m0*X01 + m1*X11 + m3*X21;
    float w1y = m1*X01 + m2*X11 + m4*X21;
    float w1z = m3*X01 + m4*X11 + m5*X21;
    float w2x = m0*X02 + m1*X12 + m3*X22;
    float w2y = m1*X02 + m2*X12 + m4*X22;
    float w2z = m3*X02 + m4*X12 + m5*X22;

    float S00 = X00*w0x + X10*w0y + X20*w0z;   // (0,0)
    float S10 = X01*w0x + X11*w0y + X21*w0z;   // (1,0)
    float S11 = X01*w1x + X11*w1y + X21*w1z;   // (1,1)
    float S20 = X02*w0x + X12*w0y + X22*w0z;   // (2,0)
    float S21 = X02*w1x + X12*w1y + X22*w1z;   // (2,1)
    float S22 = X02*w2x + X12*w2y + X22*w2z;   // (2,2)

    float* o = out + (size_t)b * 6 * HWD + vox;
    o[0]       = S00;
    o[HWD]     = S10;
    o[2 * HWD] = S11;
    o[3 * HWD] = S20;
    o[4 * HWD] = S21;
    o[5 * HWD] = S22;
}

extern "C" void kernel_launch(void* const* d_in, const int* in_sizes, int n_in,
                              void* d_out, int out_size)
{
    const float* dti = (const float*)d_in[0];
    const float* ddf = (const float*)d_in[1];
    int s0 = in_sizes[0], s1 = in_sizes[1];
    if (s0 < s1) { const float* t = dti; dti = ddf; ddf = t; int ts = s0; s0 = s1; s1 = ts; }
    int B = s1 / (3 * HWD);
    if (B > MAXB) B = MAXB;
    int total = B * HWD;
    int threads = 256;
    int blocks = (total + threads - 1) / threads;
    interleave_kernel<<<blocks, threads>>>(dti, ddf, total);
    warp_dti_kernel<<<blocks, threads>>>((float*)d_out, total);
}

// round 11
// speedup vs baseline: 1.3957x; 1.3957x over previous
#include <cuda_runtime.h>

// WarpDTI fused single-kernel (R8 layout restored — channel-planar gathers are
// warp-coalesced via z-contiguity; the R9 AoS prepass multiplied L1 wavefronts
// and regressed). Polar factor: 2 scaled Newton + 4 plain Newton iterations,
// fast-math division/μ (self-correcting iteration).

constexpr int HWD = 64 * 64 * 64;   // 262144 = 2^18

__global__ __launch_bounds__(256)
void warp_dti_kernel(const float* __restrict__ dti,
                     const float* __restrict__ ddf,
                     float* __restrict__ out,
                     int total)
{
    int idx = blockIdx.x * blockDim.x + threadIdx.x;
    if (idx >= total) return;

    int vox = idx & (HWD - 1);
    int b   = idx >> 18;
    int z   =  vox        & 63;
    int y   = (vox >> 6)  & 63;
    int x   =  vox >> 12;

    const float* u = ddf + (size_t)b * 3 * HWD;

    float u0 = __ldg(u +           vox);
    float u1 = __ldg(u +     HWD + vox);
    float u2 = __ldg(u + 2 * HWD + vox);

    // ---------- Jacobian J = I + du_i/dx_j (jnp.gradient semantics) --------
    float J00, J01, J02, J10, J11, J12, J20, J21, J22;
    {   // axis 0 (x), stride 4096
        int ip = (x < 63) ? x + 1 : 63;
        int im = (x > 0 ) ? x - 1 : 0;
        float s = (ip - im == 2) ? 0.5f : 1.0f;
        int op = (ip - x) << 12, om = (im - x) << 12;
        J00 = (__ldg(u +           vox + op) - __ldg(u +           vox + om)) * s;
        J10 = (__ldg(u + HWD     + vox + op) - __ldg(u + HWD     + vox + om)) * s;
        J20 = (__ldg(u + 2 * HWD + vox + op) - __ldg(u + 2 * HWD + vox + om)) * s;
    }
    {   // axis 1 (y), stride 64
        int ip = (y < 63) ? y + 1 : 63;
        int im = (y > 0 ) ? y - 1 : 0;
        float s = (ip - im == 2) ? 0.5f : 1.0f;
        int op = (ip - y) << 6, om = (im - y) << 6;
        J01 = (__ldg(u +           vox + op) - __ldg(u +           vox + om)) * s;
        J11 = (__ldg(u + HWD     + vox + op) - __ldg(u + HWD     + vox + om)) * s;
        J21 = (__ldg(u + 2 * HWD + vox + op) - __ldg(u + 2 * HWD + vox + om)) * s;
    }
    {   // axis 2 (z), stride 1
        int ip = (z < 63) ? z + 1 : 63;
        int im = (z > 0 ) ? z - 1 : 0;
        float s = (ip - im == 2) ? 0.5f : 1.0f;
        int op = ip - z, om = im - z;
        J02 = (__ldg(u +           vox + op) - __ldg(u +           vox + om)) * s;
        J12 = (__ldg(u + HWD     + vox + op) - __ldg(u + HWD     + vox + om)) * s;
        J22 = (__ldg(u + 2 * HWD + vox + op) - __ldg(u + 2 * HWD + vox + om)) * s;
    }
    J00 += 1.0f; J11 += 1.0f; J22 += 1.0f;

    // ---------- trilinear warp (border clamp, align_corners) ----------
    float cx = fminf(fmaxf(u0 + (float)x, 0.0f), 63.0f);
    float cy = fminf(fmaxf(u1 + (float)y, 0.0f), 63.0f);
    float cz = fminf(fmaxf(u2 + (float)z, 0.0f), 63.0f);
    float xf = floorf(cx), yf = floorf(cy), zf = floorf(cz);
    float fx = cx - xf,   fy = cy - yf,   fz = cz - zf;
    int x0 = (int)xf, y0 = (int)yf, z0 = (int)zf;
    int x1 = min(x0 + 1, 63), y1 = min(y0 + 1, 63), z1 = min(z0 + 1, 63);

    int b00 = ((x0 << 6) + y0) << 6;
    int b01 = ((x0 << 6) + y1) << 6;
    int b10 = ((x1 << 6) + y0) << 6;
    int b11 = ((x1 << 6) + y1) << 6;

    float wx0 = 1.0f - fx, wy0 = 1.0f - fy, wz0 = 1.0f - fz;
    float w000 = wx0 * wy0 * wz0, w001 = wx0 * wy0 * fz;
    float w010 = wx0 * fy  * wz0, w011 = wx0 * fy  * fz;
    float w100 = fx  * wy0 * wz0, w101 = fx  * wy0 * fz;
    float w110 = fx  * fy  * wz0, w111 = fx  * fy  * fz;

    float m[6];
    const float* img = dti + (size_t)b * 6 * HWD;
    #pragma unroll
    for (int c = 0; c < 6; c++) {
        const float* p = img + (size_t)c * HWD;
        m[c] = w000 * __ldg(p + b00 + z0) + w001 * __ldg(p + b00 + z1)
             + w010 * __ldg(p + b01 + z0) + w011 * __ldg(p + b01 + z1)
             + w100 * __ldg(p + b10 + z0) + w101 * __ldg(p + b10 + z1)
             + w110 * __ldg(p + b11 + z0) + w111 * __ldg(p + b11 + z1);
    }

    // ---------- polar factor R = U V^T ----------
    float X00 = J00, X01 = J01, X02 = J02;
    float X10 = J10, X11 = J11, X12 = J12;
    float X20 = J20, X21 = J21, X22 = J22;

    // 2 scaled Newton iterations (Frobenius mu, fast-math — self-correcting)
    #pragma unroll
    for (int it = 0; it < 2; ++it) {
        float C00 = X11 * X22 - X12 * X21;
        float C01 = X12 * X20 - X10 * X22;
        float C02 = X10 * X21 - X11 * X20;
        float C10 = X21 * X02 - X22 * X01;
        float C11 = X22 * X00 - X20 * X02;
        float C12 = X20 * X01 - X21 * X00;
        float C20 = X01 * X12 - X02 * X11;
        float C21 = X02 * X10 - X00 * X12;
        float C22 = X00 * X11 - X01 * X10;
        float det = X00 * C00 + X01 * C01 + X02 * C02;
        float adet = fmaxf(fabsf(det), 1e-12f);
        float sdet = (det < 0.0f) ? -adet : adet;
        float nX = X00*X00 + X01*X01 + X02*X02 + X10*X10 + X11*X11 + X12*X12
                 + X20*X20 + X21*X21 + X22*X22;
        float nC = C00*C00 + C01*C01 + C02*C02 + C10*C10 + C11*C11 + C12*C12
                 + C20*C20 + C21*C21 + C22*C22;
        // mu = (nC/nX)^(1/4) / sqrt(adet)  — accuracy non-critical (scaling only)
        float mu = exp2f(0.25f * __log2f(nC / nX)) * rsqrtf(adet);
        mu = fminf(fmaxf(mu, 1e-4f), 1e4f);
        float a = 0.5f * mu;
        float c = __fdividef(0.5f, mu * sdet);
        X00 = a * X00 + c * C00; X01 = a * X01 + c * C01; X02 = a * X02 + c * C02;
        X10 = a * X10 + c * C10; X11 = a * X11 + c * C11; X12 = a * X12 + c * C12;
        X20 = a * X20 + c * C20; X21 = a * X21 + c * C21; X22 = a * X22 + c * C22;
    }
    // 4 plain Newton iterations: X <- 0.5*(X + cof(X)/det)
    #pragma unroll
    for (int it = 0; it < 4; ++it) {
        float C00 = X11 * X22 - X12 * X21;
        float C01 = X12 * X20 - X10 * X22;
        float C02 = X10 * X21 - X11 * X20;
        float C10 = X21 * X02 - X22 * X01;
        float C11 = X22 * X00 - X20 * X02;
        float C12 = X20 * X01 - X21 * X00;
        float C20 = X01 * X12 - X02 * X11;
        float C21 = X02 * X10 - X00 * X12;
        float C22 = X00 * X11 - X01 * X10;
        float det = X00 * C00 + X01 * C01 + X02 * C02;
        float adet = fmaxf(fabsf(det), 1e-12f);
        float sdet = (det < 0.0f) ? -adet : adet;
        float c = __fdividef(0.5f, sdet);
        X00 = 0.5f * X00 + c * C00; X01 = 0.5f * X01 + c * C01; X02 = 0.5f * X02 + c * C02;
        X10 = 0.5f * X10 + c * C10; X11 = 0.5f * X11 + c * C11; X12 = 0.5f * X12 + c * C12;
        X20 = 0.5f * X20 + c * C20; X21 = 0.5f * X21 + c * C21; X22 = 0.5f * X22 + c * C22;
    }

    // ---------- S = R^T M R, lower triangle ----------
    float w0x = m[0]*X00 + m[1]*X10 + m[3]*X20;
    float w0y = m[1]*X00 + m[2]*X10 + m[4]*X20;
    float w0z = m[3]*X00 + m[4]*X10 + m[5]*X20;
    float w1x = m[0]*X01 + m[1]*X11 + m[3]*X21;
    float w1y = m[1]*X01 + m[2]*X11 + m[4]*X21;
    float w1z = m[3]*X01 + m[4]*X11 + m[5]*X21;
    float w2x = m[0]*X02 + m[1]*X12 + m[3]*X22;
    float w2y = m[1]*X02 + m[2]*X12 + m[4]*X22;
    float w2z = m[3]*X02 + m[4]*X12 + m[5]*X22;

    float S00 = X00*w0x + X10*w0y + X20*w0z;
    float S10 = X01*w0x + X11*w0y + X21*w0z;
    float S11 = X01*w1x + X11*w1y + X21*w1z;
    float S20 = X02*w0x + X12*w0y + X22*w0z;
    float S21 = X02*w1x + X12*w1y + X22*w1z;
    float S22 = X02*w2x + X12*w2y + X22*w2z;

    float* o = out + (size_t)b * 6 * HWD + vox;
    o[0]       = S00;
    o[HWD]     = S10;
    o[2 * HWD] = S11;
    o[3 * HWD] = S20;
    o[4 * HWD] = S21;
    o[5 * HWD] = S22;
}

extern "C" void kernel_launch(void* const* d_in, const int* in_sizes, int n_in,
                              void* d_out, int out_size)
{
    const float* dti = (const float*)d_in[0];
    const float* ddf = (const float*)d_in[1];
    int s0 = in_sizes[0], s1 = in_sizes[1];
    if (s0 < s1) { const float* t = dti; dti = ddf; ddf = t; int ts = s0; s0 = s1; s1 = ts; }
    int B = s1 / (3 * HWD);
    int total = B * HWD;
    int threads = 256;
    int blocks = (total + threads - 1) / threads;
    warp_dti_kernel<<<blocks, threads>>>(dti, ddf, (float*)d_out, total);
}